// round 4
// baseline (speedup 1.0000x reference)
#include <cuda_runtime.h>
#include <cfloat>
#include <math.h>

// Edge lists for the two MSTs (max n = 4096 -> 4095 edges each).
#define NMAX 4096
__device__ int2 g_edges[2][NMAX];

// ---------------------------------------------------------------------------
// Pre-kernel: pull both matrices into L2 (126 MB L2 vs 128 MB data -> ~98%
// residency). Runs serially before the MST kernel; L2 persists across
// launches (only L1 is flushed per launch on sm_103a).
// ---------------------------------------------------------------------------
__global__ void prefetch_kernel(const float* __restrict__ d1,
                                const float* __restrict__ d2,
                                int n)
{
    const size_t total = (size_t)n * n;            // floats per matrix
    const int nb = gridDim.x >> 1;                 // blocks per matrix
    const float* __restrict__ m = (blockIdx.x < nb) ? d1 : d2;
    const int b = blockIdx.x % nb;

    const size_t chunk = (total + nb - 1) / nb;
    const size_t start = (size_t)b * chunk;
    const size_t end   = (start + chunk < total) ? start + chunk : total;

    // one prefetch covers a 128B line (32 floats)
    for (size_t off = start + (size_t)threadIdx.x * 32;
         off < end;
         off += (size_t)blockDim.x * 32) {
        asm volatile("prefetch.global.L2 [%0];" :: "l"(m + off));
    }
}

// ---------------------------------------------------------------------------
// Prim's MST, bit-exact vs the reference (strict-< relax, FLT_MAX masking,
// argmin tie-break to lowest index). One block per matrix, 256 threads,
// 16 owned elements per thread. Single __syncthreads per iteration via
// double-buffered per-warp bests; block min recomputed redundantly by every
// thread from 8 broadcast smem entries (no second cascade/barrier).
// ---------------------------------------------------------------------------
__global__ __launch_bounds__(256, 1)
void mst_kernel(const float* __restrict__ d1,
                const float* __restrict__ d2,
                int n)
{
    const float* __restrict__ d = (blockIdx.x == 0) ? d1 : d2;
    int2* edges = g_edges[blockIdx.x];

    const int tid  = threadIdx.x;
    const int lane = tid & 31;
    const int wid  = tid >> 5;
    const int base = tid << 4;            // first of 16 owned indices

    __shared__ unsigned long long wbest[2][8];

    // ---- init: min_dist = d[0,:], parent = 0, node 0 in tree ----
    float md[16];
    int   par[16];
    {
        const float4* r0 = reinterpret_cast<const float4*>(d) + tid * 4;
        #pragma unroll
        for (int q = 0; q < 4; ++q) {
            float4 v = r0[q];
            md[q * 4 + 0] = v.x; md[q * 4 + 1] = v.y;
            md[q * 4 + 2] = v.z; md[q * 4 + 3] = v.w;
        }
    }
    #pragma unroll
    for (int k = 0; k < 16; ++k) par[k] = 0;
    if (tid == 0) md[0] = FLT_MAX;        // node 0 already in tree

    // ---- initial local argmin (value bits, lowest index on ties) ----
    unsigned lv = 0xFFFFFFFFu;
    unsigned lidx = 0;
    #pragma unroll
    for (int k = 0; k < 16; ++k) {
        unsigned u = __float_as_uint(md[k]);   // order-preserving (>=0)
        if (u < lv) { lv = u; lidx = (unsigned)(base + k); }
    }

    int buf = 0;
    for (int it = 0; it < n - 1; ++it) {
        // ---- warp argmin: two 32-bit hardware reductions ----
        unsigned vmin = __reduce_min_sync(0xffffffffu, lv);
        unsigned cand = (lv == vmin) ? lidx : 0xFFFFFFFFu;
        unsigned imin = __reduce_min_sync(0xffffffffu, cand);
        if (lane == 0)
            wbest[buf][wid] = (((unsigned long long)vmin) << 20) | imin;
        __syncthreads();

        // ---- block argmin: every thread tree-mins the 8 packed entries ----
        unsigned long long b0 = min(wbest[buf][0], wbest[buf][1]);
        unsigned long long b1 = min(wbest[buf][2], wbest[buf][3]);
        unsigned long long b2 = min(wbest[buf][4], wbest[buf][5]);
        unsigned long long b3 = min(wbest[buf][6], wbest[buf][7]);
        unsigned long long bb = min(min(b0, b1), min(b2, b3));
        const int j = (int)(bb & 0xFFFFFu);

        // ---- issue the row load ASAP (L2-resident after prefetch);
        //      evict-first: this row is dead after consumption ----
        const float4* rp =
            reinterpret_cast<const float4*>(d + (size_t)j * n) + tid * 4;
        float4 v0 = __ldcs(rp + 0);
        float4 v1 = __ldcs(rp + 1);
        float4 v2 = __ldcs(rp + 2);
        float4 v3 = __ldcs(rp + 3);

        // ---- owner records edge (parent BEFORE relax), marks j in-tree ----
        if ((j >> 4) == tid) {
            edges[it] = make_int2(par[j & 15], j);
            md[j & 15] = FLT_MAX;
        }

        // ---- relax (strict <, skip in-tree) fused with local argmin ----
        float v[16] = { v0.x, v0.y, v0.z, v0.w,
                        v1.x, v1.y, v1.z, v1.w,
                        v2.x, v2.y, v2.z, v2.w,
                        v3.x, v3.y, v3.z, v3.w };
        lv = 0xFFFFFFFFu; lidx = (unsigned)base;
        #pragma unroll
        for (int k = 0; k < 16; ++k) {
            float mk = md[k];
            if (mk != FLT_MAX && v[k] < mk) {
                mk = v[k];
                par[k] = j;
                md[k] = mk;
            }
            unsigned u = __float_as_uint(mk);
            if (u < lv) { lv = u; lidx = (unsigned)(base + k); }
        }

        buf ^= 1;
    }
}

// ---------------------------------------------------------------------------
// Gather both signatures and reduce:
//   result = sum_{e in p1}(d1[e]-d2[e])^2 + sum_{e in p2}(d1[e]-d2[e])^2
// ---------------------------------------------------------------------------
__global__ __launch_bounds__(1024, 1)
void finalize_kernel(const float* __restrict__ d1,
                     const float* __restrict__ d2,
                     float* __restrict__ out,
                     int n)
{
    __shared__ float warp_sums[32];
    const int tid = threadIdx.x;

    float acc = 0.0f;
    for (int i = tid; i < n - 1; i += blockDim.x) {
        int2 e1 = g_edges[0][i];
        int2 e2 = g_edges[1][i];
        size_t o1 = (size_t)e1.x * n + e1.y;
        size_t o2 = (size_t)e2.x * n + e2.y;
        float a = d1[o1] - d2[o1];
        float b = d1[o2] - d2[o2];
        acc += a * a + b * b;
    }
    #pragma unroll
    for (int o = 16; o; o >>= 1)
        acc += __shfl_xor_sync(0xffffffffu, acc, o);
    if ((tid & 31) == 0) warp_sums[tid >> 5] = acc;
    __syncthreads();
    if (tid < 32) {
        float v = (tid < (int)(blockDim.x >> 5)) ? warp_sums[tid] : 0.0f;
        #pragma unroll
        for (int o = 16; o; o >>= 1)
            v += __shfl_xor_sync(0xffffffffu, v, o);
        if (tid == 0) out[0] = v;
    }
}

extern "C" void kernel_launch(void* const* d_in, const int* in_sizes, int n_in,
                              void* d_out, int out_size)
{
    const float* d1 = (const float*)d_in[0];
    const float* d2 = (const float*)d_in[1];
    float* out = (float*)d_out;

    const int n = (int)lrint(sqrt((double)in_sizes[0]));   // 4096

    prefetch_kernel<<<64, 1024>>>(d1, d2, n);
    mst_kernel<<<2, 256>>>(d1, d2, n);
    finalize_kernel<<<1, 1024>>>(d1, d2, out, n);
}

// round 9
// speedup vs baseline: 1.1621x; 1.1621x over previous
#include <cuda_runtime.h>
#include <cfloat>
#include <math.h>

// Edge lists for the two MSTs (max n = 4096 -> 4095 edges each).
#define NMAX 4096
__device__ int2 g_edges[2][NMAX];

// ---------------------------------------------------------------------------
// Pre-kernel: pull both matrices into L2 (~126 MB L2 vs 128 MB data).
// Measured R4: 13.7 us @ 5.6 TB/s. L2 persists across launches.
// ---------------------------------------------------------------------------
__global__ void prefetch_kernel(const float* __restrict__ d1,
                                const float* __restrict__ d2,
                                int n)
{
    const size_t total = (size_t)n * n;            // floats per matrix
    const int nb = gridDim.x >> 1;                 // blocks per matrix
    const float* __restrict__ m = (blockIdx.x < nb) ? d1 : d2;
    const int b = blockIdx.x % nb;

    const size_t chunk = (total + nb - 1) / nb;
    const size_t start = (size_t)b * chunk;
    const size_t end   = (start + chunk < total) ? start + chunk : total;

    for (size_t off = start + (size_t)threadIdx.x * 32;
         off < end;
         off += (size_t)blockDim.x * 32) {
        asm volatile("prefetch.global.L2 [%0];" :: "l"(m + off));
    }
}

// ---------------------------------------------------------------------------
// Prim's MST, bit-exact vs the reference (strict-< relax, FLT_MAX masking,
// argmin tie-break to lowest index). One block per matrix, 512 threads,
// 8 owned elements per thread — ALL array indexing is compile-time (fully
// unrolled, predicated) so md[]/par[] stay in registers (R3's spill bug).
// One __syncthreads per iteration: 16 warp leaders publish packed u64 bests,
// every thread redundantly tree-mins the 16 broadcast smem entries.
// ---------------------------------------------------------------------------
__global__ __launch_bounds__(512, 1)
void mst_kernel(const float* __restrict__ d1,
                const float* __restrict__ d2,
                int n)
{
    const float* __restrict__ d = (blockIdx.x == 0) ? d1 : d2;
    int2* edges = g_edges[blockIdx.x];

    const int tid  = threadIdx.x;
    const int lane = tid & 31;
    const int wid  = tid >> 5;
    const int base = tid << 3;            // first of 8 owned indices

    __shared__ unsigned long long wbest[2][16];

    // ---- init: min_dist = d[0,:], parent = 0, node 0 in tree ----
    float md[8];
    int   par[8];
    {
        const float4* r0 = reinterpret_cast<const float4*>(d) + tid * 2;
        float4 a = r0[0], b = r0[1];
        md[0] = a.x; md[1] = a.y; md[2] = a.z; md[3] = a.w;
        md[4] = b.x; md[5] = b.y; md[6] = b.z; md[7] = b.w;
    }
    #pragma unroll
    for (int k = 0; k < 8; ++k) par[k] = 0;
    if (tid == 0) md[0] = FLT_MAX;        // node 0 already in tree

    // ---- initial local argmin: packed u64 (valuebits<<32 | idx) min-tree.
    //      float bits are order-preserving for non-negative values; min on
    //      the packed key -> lowest value, then lowest index (== jnp.argmin).
    unsigned long long lkey;
    {
        unsigned long long k0, k1, k2, k3;
        #define PKEY(K) ((((unsigned long long)__float_as_uint(md[K])) << 32) \
                         | (unsigned)(base + (K)))
        k0 = min(PKEY(0), PKEY(1));
        k1 = min(PKEY(2), PKEY(3));
        k2 = min(PKEY(4), PKEY(5));
        k3 = min(PKEY(6), PKEY(7));
        lkey = min(min(k0, k1), min(k2, k3));
    }

    int buf = 0;
    for (int it = 0; it < n - 1; ++it) {
        // ---- warp argmin: two dependent 32-bit hardware reductions ----
        const unsigned lv = (unsigned)(lkey >> 32);
        const unsigned vmin = __reduce_min_sync(0xffffffffu, lv);
        const unsigned cand = (lv == vmin) ? (unsigned)lkey : 0xFFFFFFFFu;
        const unsigned imin = __reduce_min_sync(0xffffffffu, cand);
        if (lane == 0)
            wbest[buf][wid] = (((unsigned long long)vmin) << 32) | imin;
        __syncthreads();

        // ---- block argmin: every thread tree-mins 16 broadcast entries ----
        const unsigned long long* wb = wbest[buf];
        unsigned long long a0 = min(wb[0],  wb[1]);
        unsigned long long a1 = min(wb[2],  wb[3]);
        unsigned long long a2 = min(wb[4],  wb[5]);
        unsigned long long a3 = min(wb[6],  wb[7]);
        unsigned long long a4 = min(wb[8],  wb[9]);
        unsigned long long a5 = min(wb[10], wb[11]);
        unsigned long long a6 = min(wb[12], wb[13]);
        unsigned long long a7 = min(wb[14], wb[15]);
        a0 = min(a0, a1); a2 = min(a2, a3); a4 = min(a4, a5); a6 = min(a6, a7);
        const unsigned long long bb = min(min(a0, a2), min(a4, a6));
        const int j = (int)(unsigned)bb;   // low word = global argmin index

        // ---- issue the row load ASAP (L2-resident; evict-first: dead
        //      after consumption, protects unread rows) ----
        const float4* rp =
            reinterpret_cast<const float4*>(d + (size_t)j * n) + tid * 2;
        const float4 v0 = __ldcs(rp + 0);
        const float4 v1 = __ldcs(rp + 1);

        // ---- owner records edge (parent BEFORE relax) and marks j
        //      in-tree. Static indices only -> stays in registers. ----
        const bool owner = ((j >> 3) == tid);
        if (owner) {
            const int jj = j & 7;
            #pragma unroll
            for (int k = 0; k < 8; ++k) {
                if (jj == k) {
                    edges[it] = make_int2(par[k], j);
                    md[k] = FLT_MAX;
                }
            }
        }

        // ---- relax (strict <, skip in-tree) fused with local argmin ----
        const float v[8] = { v0.x, v0.y, v0.z, v0.w,
                             v1.x, v1.y, v1.z, v1.w };
        #pragma unroll
        for (int k = 0; k < 8; ++k) {
            if (md[k] != FLT_MAX && v[k] < md[k]) {
                md[k]  = v[k];
                par[k] = j;
            }
        }
        {
            unsigned long long k0, k1, k2, k3;
            k0 = min(PKEY(0), PKEY(1));
            k1 = min(PKEY(2), PKEY(3));
            k2 = min(PKEY(4), PKEY(5));
            k3 = min(PKEY(6), PKEY(7));
            lkey = min(min(k0, k1), min(k2, k3));
        }

        buf ^= 1;
    }
    #undef PKEY
}

// ---------------------------------------------------------------------------
// Gather both signatures and reduce:
//   result = sum_{e in p1}(d1[e]-d2[e])^2 + sum_{e in p2}(d1[e]-d2[e])^2
// ---------------------------------------------------------------------------
__global__ __launch_bounds__(1024, 1)
void finalize_kernel(const float* __restrict__ d1,
                     const float* __restrict__ d2,
                     float* __restrict__ out,
                     int n)
{
    __shared__ float warp_sums[32];
    const int tid = threadIdx.x;

    float acc = 0.0f;
    for (int i = tid; i < n - 1; i += blockDim.x) {
        int2 e1 = g_edges[0][i];
        int2 e2 = g_edges[1][i];
        size_t o1 = (size_t)e1.x * n + e1.y;
        size_t o2 = (size_t)e2.x * n + e2.y;
        float a = d1[o1] - d2[o1];
        float b = d1[o2] - d2[o2];
        acc += a * a + b * b;
    }
    #pragma unroll
    for (int o = 16; o; o >>= 1)
        acc += __shfl_xor_sync(0xffffffffu, acc, o);
    if ((tid & 31) == 0) warp_sums[tid >> 5] = acc;
    __syncthreads();
    if (tid < 32) {
        float v = (tid < (int)(blockDim.x >> 5)) ? warp_sums[tid] : 0.0f;
        #pragma unroll
        for (int o = 16; o; o >>= 1)
            v += __shfl_xor_sync(0xffffffffu, v, o);
        if (tid == 0) out[0] = v;
    }
}

extern "C" void kernel_launch(void* const* d_in, const int* in_sizes, int n_in,
                              void* d_out, int out_size)
{
    const float* d1 = (const float*)d_in[0];
    const float* d2 = (const float*)d_in[1];
    float* out = (float*)d_out;

    const int n = (int)lrint(sqrt((double)in_sizes[0]));   // 4096

    prefetch_kernel<<<64, 1024>>>(d1, d2, n);
    mst_kernel<<<2, 512>>>(d1, d2, n);
    finalize_kernel<<<1, 1024>>>(d1, d2, out, n);
}